// round 14
// baseline (speedup 1.0000x reference)
#include <cuda_runtime.h>
#include <cuda_bf16.h>

// Problem constants (fixed shapes per reference)
#define NN 100000
#define EE 600000
#define HH 128
#define GG 4000
#define TT 128

#define SCAN_B 512
#define NB ((NN + SCAN_B - 1) / SCAN_B)   // 196 scan blocks

// Scratch (allocation-free: device globals)
__device__ float g_deg[NN];                 // dinv
__device__ float g_h[(size_t)NN * HH];
__device__ float g_t[(size_t)NN * HH];      // T' = dinv * (A@B)
__device__ float g_o[(size_t)NN * HH];
__device__ float g_pool[(size_t)GG * HH];
__device__ float g_cnt[GG];
__device__ int   g_cnti[NN];                // in-degree counts
__device__ int   g_cur[NN];                 // fill cursors
__device__ int   g_rs[NN + 1];              // CSR row starts
__device__ int   g_csr[EE];                 // CSR src indices
__device__ int   g_bsum[NB];                // per-block sums for scan

__constant__ int c_off[9] = {0, 119, 124, 136, 148, 158, 164, 170, 172};

// ---------------------------------------------------------------------------
// CSR build
__global__ void count_zero_kernel() {
    int i = blockIdx.x * blockDim.x + threadIdx.x;
    if (i < NN) { g_cnti[i] = 0; g_cur[i] = 0; }
}

__global__ void count_kernel(const int* __restrict__ dst) {
    int e = blockIdx.x * blockDim.x + threadIdx.x;
    if (e < EE) atomicAdd(&g_cnti[dst[e]], 1);
}

__global__ void blocksum_kernel() {        // NB blocks x SCAN_B threads
    __shared__ int s[SCAN_B];
    const int n = blockIdx.x * SCAN_B + threadIdx.x;
    s[threadIdx.x] = (n < NN) ? g_cnti[n] : 0;
    __syncthreads();
    for (int off = SCAN_B / 2; off > 0; off >>= 1) {
        if (threadIdx.x < off) s[threadIdx.x] += s[threadIdx.x + off];
        __syncthreads();
    }
    if (threadIdx.x == 0) g_bsum[blockIdx.x] = s[0];
}

__global__ void scanblock_kernel() {       // 1 block x 256 threads, NB<=256
    __shared__ int s[256];
    const int t = threadIdx.x;
    const int v = (t < NB) ? g_bsum[t] : 0;
    s[t] = v;
    __syncthreads();
    for (int off = 1; off < 256; off <<= 1) {
        int u = (t >= off) ? s[t - off] : 0;
        __syncthreads();
        s[t] += u;
        __syncthreads();
    }
    if (t < NB) g_bsum[t] = s[t] - v;       // exclusive
}

__global__ void rowstart_kernel() {        // NB blocks x SCAN_B threads
    __shared__ int s[SCAN_B];
    const int t = threadIdx.x;
    const int n = blockIdx.x * SCAN_B + t;
    const int v = (n < NN) ? g_cnti[n] : 0;
    s[t] = v;
    __syncthreads();
    for (int off = 1; off < SCAN_B; off <<= 1) {
        int u = (t >= off) ? s[t - off] : 0;
        __syncthreads();
        s[t] += u;
        __syncthreads();
    }
    if (n < NN) {
        g_rs[n] = s[t] - v + g_bsum[blockIdx.x];           // exclusive prefix
        g_deg[n] = rsqrtf((float)v + 1.0f);                // dinv (self-loop)
    }
    if (blockIdx.x == 0 && t == 0) g_rs[NN] = EE;
}

__global__ void fill_kernel(const int* __restrict__ src, const int* __restrict__ dst) {
    int e = blockIdx.x * blockDim.x + threadIdx.x;
    if (e >= EE) return;
    const int d = dst[e];
    const int pos = g_rs[d] + atomicAdd(&g_cur[d], 1);
    g_csr[pos] = src[e];
}

// ---------------------------------------------------------------------------
// AtomEncoder: h[n] = sum_f emb[x[n,f]+off[f]]
__global__ void embed_kernel(const int* __restrict__ x, const float* __restrict__ emb) {
    int n = blockIdx.x;
    int t = threadIdx.x;
    __shared__ int xi[9];
    if (t < 9) xi[t] = x[n * 9 + t] + c_off[t];
    __syncthreads();
    float v = 0.0f;
#pragma unroll
    for (int f = 0; f < 9; f++) v += emb[(size_t)xi[f] * HH + t];
    g_h[(size_t)n * HH + t] = v;
}

// ---------------------------------------------------------------------------
// Persistent GEMM: K-pair packed f32x2, 512 threads, 4 rows x 8 cols / thread.
// MODE 0: layer. Epilogue stores ONLY T'[r] = dinv[r] * (A@B)[r].
// MODE 2: final. Epilogue: OUT = (A@B)/max(cnt,1) + bias.
template <int MODE>
__global__ void __launch_bounds__(512, 1)
gemm_kernel(const float* __restrict__ A, const float* __restrict__ B,
            const float* __restrict__ bias, float* __restrict__ T,
            float* __restrict__ OUT, int M, int numTiles) {
    extern __shared__ float sm[];
    const int tid = threadIdx.x;              // 512 threads
    const int tx = tid & 15;                  // 16 col groups
    const int ty = tid >> 4;                  // 32 row groups
    const int r0t = ty << 2;                  // 4 rows / thread

    // Stage first A tile into buffer 0 (async).
    int tile = blockIdx.x;
    {
        const int row0 = tile * 128;
        float* dst = sm + 16384;
#pragma unroll
        for (int i = tid; i < 4096; i += 512) {
            const int r = i >> 5, c = (i & 31) << 2;
            const int gr = row0 + r;
            const float* gp = (gr < M) ? (A + (size_t)gr * HH + c) : A;
            const int sz = (gr < M) ? 16 : 0;
            const unsigned int d = (unsigned int)__cvta_generic_to_shared(&dst[r * 128 + c]);
            asm volatile("cp.async.cg.shared.global [%0], [%1], 16, %2;"
                         :: "r"(d), "l"(gp), "r"(sz));
        }
        asm volatile("cp.async.commit_group;");
    }

    // Build Bp (k-pair interleave of B), overlapping the A load.
    {
        float2* Bp = (float2*)sm;
#pragma unroll
        for (int i = tid; i < 8192; i += 512) {
            const int kk = i >> 7, c = i & 127;
            Bp[i] = make_float2(B[(2 * kk) * 128 + c], B[(2 * kk + 1) * 128 + c]);
        }
    }

    float bsv[8];
    if (MODE == 2) {
#pragma unroll
        for (int q = 0; q < 4; q++) {
            const float2 b2 = *(const float2*)&bias[32 * q + 2 * tx];
            bsv[2 * q] = b2.x; bsv[2 * q + 1] = b2.y;
        }
    }

    asm volatile("cp.async.wait_group 0;");
    __syncthreads();

    int buf = 0;
    const unsigned long long* BpU = (const unsigned long long*)sm;

    for (; tile < numTiles; tile += gridDim.x) {
        const int next = tile + gridDim.x;
        if (next < numTiles) {
            const int row0n = next * 128;
            float* dst = sm + 16384 + ((buf ^ 1) << 14);
#pragma unroll
            for (int i = tid; i < 4096; i += 512) {
                const int r = i >> 5, c = (i & 31) << 2;
                const int gr = row0n + r;
                const float* gp = (gr < M) ? (A + (size_t)gr * HH + c) : A;
                const int sz = (gr < M) ? 16 : 0;
                const unsigned int d = (unsigned int)__cvta_generic_to_shared(&dst[r * 128 + c]);
                asm volatile("cp.async.cg.shared.global [%0], [%1], 16, %2;"
                             :: "r"(d), "l"(gp), "r"(sz));
            }
            asm volatile("cp.async.commit_group;");
        }

        const float* As = sm + 16384 + (buf << 14);
        unsigned long long acc[4][8];
#pragma unroll
        for (int i = 0; i < 4; i++)
#pragma unroll
            for (int j = 0; j < 8; j++) acc[i][j] = 0ull;

#pragma unroll 2
        for (int kk = 0; kk < 64; kk++) {
            unsigned long long y[8];
            {
                const unsigned long long* yb = BpU + kk * 128 + 2 * tx;
                const ulonglong2 t0 = *(const ulonglong2*)(yb);
                const ulonglong2 t1 = *(const ulonglong2*)(yb + 32);
                const ulonglong2 t2 = *(const ulonglong2*)(yb + 64);
                const ulonglong2 t3 = *(const ulonglong2*)(yb + 96);
                y[0] = t0.x; y[1] = t0.y; y[2] = t1.x; y[3] = t1.y;
                y[4] = t2.x; y[5] = t2.y; y[6] = t3.x; y[7] = t3.y;
            }
#pragma unroll
            for (int i = 0; i < 4; i++) {
                const unsigned long long x =
                    *(const unsigned long long*)(As + (r0t + i) * 128 + 2 * kk);
#pragma unroll
                for (int j = 0; j < 8; j++)
                    asm("fma.rn.f32x2 %0, %1, %2, %0;" : "+l"(acc[i][j]) : "l"(x), "l"(y[j]));
            }
        }

        const int row0 = tile * 128;
#pragma unroll
        for (int i = 0; i < 4; i++) {
            const int r = row0 + r0t + i;
            if (r >= M) continue;
            float vv[8];
#pragma unroll
            for (int j = 0; j < 8; j++) {
                float lo, hi;
                asm("mov.b64 {%0, %1}, %2;" : "=f"(lo), "=f"(hi) : "l"(acc[i][j]));
                vv[j] = lo + hi;
            }
            if (MODE == 2) {
                const float s = 1.0f / fmaxf(g_cnt[r], 1.0f);
#pragma unroll
                for (int q = 0; q < 4; q++) {
                    float2 o;
                    o.x = fmaf(s, vv[2 * q], bsv[2 * q]);
                    o.y = fmaf(s, vv[2 * q + 1], bsv[2 * q + 1]);
                    *(float2*)&OUT[(size_t)r * TT + 32 * q + 2 * tx] = o;
                }
            } else {
                const float d = g_deg[r];   // dinv
#pragma unroll
                for (int q = 0; q < 4; q++) {
                    float2 t2;
                    t2.x = d * vv[2 * q];
                    t2.y = d * vv[2 * q + 1];
                    *(float2*)&T[(size_t)r * HH + 32 * q + 2 * tx] = t2;
                }
            }
        }

        asm volatile("cp.async.wait_group 0;");
        __syncthreads();
        buf ^= 1;
    }
}

// ---------------------------------------------------------------------------
// Aggregator: one warp / node.  OUT[n] = dinv_n * (sum_{s->n} T'[s] + T'[n]) + bias
// RELU: apply relu on write (layers 1,2 feed relu'd input to the next GEMM).
template <bool RELU>
__global__ void agg_kernel(const float* __restrict__ Tp, const float* __restrict__ bias,
                           float* __restrict__ OUT) {
    const int n = (blockIdx.x * blockDim.x + threadIdx.x) >> 5;
    const int lane = threadIdx.x & 31;
    if (n >= NN) return;
    const int c = lane << 2;

    float4 acc = *(const float4*)(Tp + (size_t)n * HH + c);   // self term
    int i = g_rs[n];
    const int end = g_rs[n + 1];
    for (; i + 1 < end; i += 2) {
        const int s0 = g_csr[i];
        const int s1 = g_csr[i + 1];
        const float4 v0 = *(const float4*)(Tp + (size_t)s0 * HH + c);
        const float4 v1 = *(const float4*)(Tp + (size_t)s1 * HH + c);
        acc.x += v0.x; acc.y += v0.y; acc.z += v0.z; acc.w += v0.w;
        acc.x += v1.x; acc.y += v1.y; acc.z += v1.z; acc.w += v1.w;
    }
    if (i < end) {
        const int s0 = g_csr[i];
        const float4 v0 = *(const float4*)(Tp + (size_t)s0 * HH + c);
        acc.x += v0.x; acc.y += v0.y; acc.z += v0.z; acc.w += v0.w;
    }

    const float d = g_deg[n];
    const float4 b = *(const float4*)(bias + c);
    float4 o;
    o.x = fmaf(d, acc.x, b.x);
    o.y = fmaf(d, acc.y, b.y);
    o.z = fmaf(d, acc.z, b.z);
    o.w = fmaf(d, acc.w, b.w);
    if (RELU) {
        o.x = fmaxf(o.x, 0.f); o.y = fmaxf(o.y, 0.f);
        o.z = fmaxf(o.z, 0.f); o.w = fmaxf(o.w, 0.f);
    }
    *(float4*)(OUT + (size_t)n * HH + c) = o;
}

// ---------------------------------------------------------------------------
__global__ void pool_zero_kernel() {
    int i = blockIdx.x * blockDim.x + threadIdx.x;
    if (i < GG * HH) g_pool[i] = 0.0f;
    if (i < GG) g_cnt[i] = 0.0f;
}

// one warp / node: pooled[batch[n]] += h[n]; cnt[batch[n]] += 1
__global__ void pool_scatter_kernel(const int* __restrict__ batch, const float* __restrict__ h) {
    const int n = (blockIdx.x * blockDim.x + threadIdx.x) >> 5;
    const int lane = threadIdx.x & 31;
    if (n >= NN) return;
    const int g = batch[n];
    float4 v = *(const float4*)(h + (size_t)n * HH + (lane << 2));
    float* p = g_pool + (size_t)g * HH + (lane << 2);
    asm volatile("red.global.add.v4.f32 [%0], {%1,%2,%3,%4};"
                 :: "l"(p), "f"(v.x), "f"(v.y), "f"(v.z), "f"(v.w)
                 : "memory");
    if (lane == 0) atomicAdd(&g_cnt[g], 1.0f);
}

// ---------------------------------------------------------------------------
extern "C" void kernel_launch(void* const* d_in, const int* in_sizes, int n_in,
                              void* d_out, int out_size) {
    const int*   x     = (const int*)d_in[0];
    const int*   ei    = (const int*)d_in[1];
    const int*   batch = (const int*)d_in[2];
    const float* emb   = (const float*)d_in[3];
    const float* W1    = (const float*)d_in[4];
    const float* b1    = (const float*)d_in[5];
    const float* W2    = (const float*)d_in[6];
    const float* b2    = (const float*)d_in[7];
    const float* W3    = (const float*)d_in[8];
    const float* b3    = (const float*)d_in[9];
    const float* Wl    = (const float*)d_in[10];
    const float* bl    = (const float*)d_in[11];
    float* out = (float*)d_out;

    const int* srcp = ei;
    const int* dstp = ei + EE;

    float *p_h, *p_t, *p_o, *p_pool;
    cudaGetSymbolAddress((void**)&p_h, g_h);
    cudaGetSymbolAddress((void**)&p_t, g_t);
    cudaGetSymbolAddress((void**)&p_o, g_o);
    cudaGetSymbolAddress((void**)&p_pool, g_pool);

    const int SMEM = 3 * 128 * 128 * (int)sizeof(float);   // 192KB: Bp + 2x A buffers
    static bool attr_set = false;
    if (!attr_set) {
        cudaFuncSetAttribute(gemm_kernel<0>, cudaFuncAttributeMaxDynamicSharedMemorySize, SMEM);
        cudaFuncSetAttribute(gemm_kernel<2>, cudaFuncAttributeMaxDynamicSharedMemorySize, SMEM);
        attr_set = true;
    }

    // ---- CSR build (also computes dinv) ----
    count_zero_kernel<<<(NN + 255) / 256, 256>>>();
    count_kernel<<<(EE + 255) / 256, 256>>>(dstp);
    blocksum_kernel<<<NB, SCAN_B>>>();
    scanblock_kernel<<<1, 256>>>();
    rowstart_kernel<<<NB, SCAN_B>>>();
    fill_kernel<<<(EE + 255) / 256, 256>>>(srcp, dstp);

    // atom embedding sum
    embed_kernel<<<NN, 128>>>(x, emb);

    const int tilesN = (NN + 127) / 128;      // 782
    const int tilesG = (GG + 127) / 128;      // 32
    const int gridN = tilesN < 148 ? tilesN : 148;
    const int gridG = tilesG < 148 ? tilesG : 148;
    const int agg_blocks = (NN * 32 + 255) / 256;

    // Layer 1: t' = dinv*(h@W1); o = relu(agg(t') + b1)
    gemm_kernel<0><<<gridN, 512, SMEM>>>(p_h, W1, nullptr, p_t, nullptr, NN, tilesN);
    agg_kernel<true><<<agg_blocks, 256>>>(p_t, b1, p_o);

    // Layer 2: t' = dinv*(o@W2); h = relu(agg(t') + b2)
    gemm_kernel<0><<<gridN, 512, SMEM>>>(p_o, W2, nullptr, p_t, nullptr, NN, tilesN);
    agg_kernel<true><<<agg_blocks, 256>>>(p_t, b2, p_h);

    // Layer 3: t' = dinv*(h@W3); o = agg(t') + b3   (no relu)
    gemm_kernel<0><<<gridN, 512, SMEM>>>(p_h, W3, nullptr, p_t, nullptr, NN, tilesN);
    agg_kernel<false><<<agg_blocks, 256>>>(p_t, b3, p_o);

    // Mean pool + final linear
    pool_zero_kernel<<<(GG * HH + 255) / 256, 256>>>();
    pool_scatter_kernel<<<(NN * 32 + 255) / 256, 256>>>(batch, p_o);
    gemm_kernel<2><<<gridG, 512, SMEM>>>(p_pool, Wl, bl, nullptr, out, GG, tilesG);
}

// round 16
// speedup vs baseline: 1.4332x; 1.4332x over previous
#include <cuda_runtime.h>
#include <cuda_bf16.h>
#include <cstdint>

// Problem constants (fixed shapes per reference)
#define NN 100000
#define EE 600000
#define HH 128
#define GG 4000
#define TT 128

#define SCAN_B 512
#define NB ((NN + SCAN_B - 1) / SCAN_B)

// Scratch (allocation-free: device globals)
__device__ float g_deg[NN];                       // dinv
__device__ float g_t[(size_t)NN * HH];            // T' = dinv * (A@B)
__device__ float g_o[(size_t)NN * HH];            // layer-3 output (fp32, for pool)
__device__ __nv_bfloat16 g_ah[(size_t)NN * HH];   // activation split hi
__device__ __nv_bfloat16 g_al[(size_t)NN * HH];   // activation split lo
__device__ float g_pool[(size_t)GG * HH];
__device__ float g_cnt[GG];
__device__ int   g_cnti[NN];
__device__ int   g_cur[NN];
__device__ int   g_rs[NN + 1];
__device__ int   g_csr[EE];
__device__ int   g_bsum[NB];

__constant__ int c_off[9] = {0, 119, 124, 136, 148, 158, 164, 170, 172};

// ---------------------------------------------------------------------------
// CSR build
__global__ void count_zero_kernel() {
    int i = blockIdx.x * blockDim.x + threadIdx.x;
    if (i < NN) { g_cnti[i] = 0; g_cur[i] = 0; }
}
__global__ void count_kernel(const int* __restrict__ dst) {
    int e = blockIdx.x * blockDim.x + threadIdx.x;
    if (e < EE) atomicAdd(&g_cnti[dst[e]], 1);
}
__global__ void blocksum_kernel() {
    __shared__ int s[SCAN_B];
    const int n = blockIdx.x * SCAN_B + threadIdx.x;
    s[threadIdx.x] = (n < NN) ? g_cnti[n] : 0;
    __syncthreads();
    for (int off = SCAN_B / 2; off > 0; off >>= 1) {
        if (threadIdx.x < off) s[threadIdx.x] += s[threadIdx.x + off];
        __syncthreads();
    }
    if (threadIdx.x == 0) g_bsum[blockIdx.x] = s[0];
}
__global__ void scanblock_kernel() {
    __shared__ int s[256];
    const int t = threadIdx.x;
    const int v = (t < NB) ? g_bsum[t] : 0;
    s[t] = v;
    __syncthreads();
    for (int off = 1; off < 256; off <<= 1) {
        int u = (t >= off) ? s[t - off] : 0;
        __syncthreads();
        s[t] += u;
        __syncthreads();
    }
    if (t < NB) g_bsum[t] = s[t] - v;
}
__global__ void rowstart_kernel() {
    __shared__ int s[SCAN_B];
    const int t = threadIdx.x;
    const int n = blockIdx.x * SCAN_B + t;
    const int v = (n < NN) ? g_cnti[n] : 0;
    s[t] = v;
    __syncthreads();
    for (int off = 1; off < SCAN_B; off <<= 1) {
        int u = (t >= off) ? s[t - off] : 0;
        __syncthreads();
        s[t] += u;
        __syncthreads();
    }
    if (n < NN) {
        g_rs[n] = s[t] - v + g_bsum[blockIdx.x];
        g_deg[n] = rsqrtf((float)v + 1.0f);
    }
    if (blockIdx.x == 0 && t == 0) g_rs[NN] = EE;
}
__global__ void fill_kernel(const int* __restrict__ src, const int* __restrict__ dst) {
    int e = blockIdx.x * blockDim.x + threadIdx.x;
    if (e >= EE) return;
    const int d = dst[e];
    const int pos = g_rs[d] + atomicAdd(&g_cur[d], 1);
    g_csr[pos] = src[e];
}

// ---------------------------------------------------------------------------
// AtomEncoder: writes split bf16 activation
__global__ void embed_kernel(const int* __restrict__ x, const float* __restrict__ emb) {
    int n = blockIdx.x;
    int t = threadIdx.x;
    __shared__ int xi[9];
    if (t < 9) xi[t] = x[n * 9 + t] + c_off[t];
    __syncthreads();
    float v = 0.0f;
#pragma unroll
    for (int f = 0; f < 9; f++) v += emb[(size_t)xi[f] * HH + t];
    const __nv_bfloat16 hi = __float2bfloat16(v);
    const __nv_bfloat16 lo = __float2bfloat16(v - __bfloat162float(hi));
    g_ah[(size_t)n * HH + t] = hi;
    g_al[(size_t)n * HH + t] = lo;
}

// ---------------------------------------------------------------------------
// mma.sync helpers (base ISA — works on compute_103 target)
__device__ __forceinline__ void mma16816(float* c, const uint32_t* a,
                                         uint32_t b0, uint32_t b1) {
    asm volatile(
        "mma.sync.aligned.m16n8k16.row.col.f32.bf16.bf16.f32 "
        "{%0,%1,%2,%3}, {%4,%5,%6,%7}, {%8,%9}, {%0,%1,%2,%3};"
        : "+f"(c[0]), "+f"(c[1]), "+f"(c[2]), "+f"(c[3])
        : "r"(a[0]), "r"(a[1]), "r"(a[2]), "r"(a[3]), "r"(b0), "r"(b1));
}
__device__ __forceinline__ void ldm_x4(uint32_t* r, uint32_t addr) {
    asm volatile("ldmatrix.sync.aligned.m8n8.x4.shared.b16 {%0,%1,%2,%3}, [%4];"
                 : "=r"(r[0]), "=r"(r[1]), "=r"(r[2]), "=r"(r[3]) : "r"(addr));
}
__device__ __forceinline__ uint32_t smem_u32(const void* p) {
    uint32_t a;
    asm("{ .reg .u64 t; cvta.to.shared.u64 t, %1; cvt.u32.u64 %0, t; }" : "=r"(a) : "l"(p));
    return a;
}
__device__ __forceinline__ uint32_t bf2pack(float lo, float hi) {
    __nv_bfloat162 p;
    p.x = __float2bfloat16(lo);
    p.y = __float2bfloat16(hi);
    return *(uint32_t*)&p;
}

// smem map (bytes): Bh pack [0,32768), Bl pack [32768,65536),
// A tiles: buf b, split s at 65536 + b*69632 + s*34816 (row stride 272B).
#define SMB_BH 0
#define SMB_BL 32768
#define SMB_A  65536
#define A_STRIDE_B 272
#define A_SPLIT_B 34816
#define A_BUF_B 69632
#define SMEM_MMA (65536 + 2 * A_BUF_B)   // 204800

// ---------------------------------------------------------------------------
// HMMA layer GEMM (persistent): T'[r] = dinv[r] * (A @ W)[r]
// A as bf16 split (Ah+Al); computes Ah*Wh + Ah*Wl + Al*Wh, fp32 accum in regs.
// 256 threads = 8 warps; warp w owns rows [w*16, w*16+16) x all 128 cols.
__global__ void __launch_bounds__(256, 1)
gemm_mma_kernel(const __nv_bfloat16* __restrict__ Ah, const __nv_bfloat16* __restrict__ Al,
                const float* __restrict__ W, float* __restrict__ T, int M, int numTiles) {
    extern __shared__ char smc[];
    const uint32_t smb = smem_u32(smc);
    const int tid = threadIdx.x;
    const int w = tid >> 5;
    const int lane = tid & 31;

    // Stage first A tile (buffer 0): 16B chunks into padded rows.
    int tile = blockIdx.x;
    {
        const int row0 = tile * 128;
#pragma unroll
        for (int i = tid; i < 4096; i += 256) {
            const int msel = i >> 11;            // 0 = hi, 1 = lo
            const int j = i & 2047;
            const int r = j >> 4, c0 = (j & 15) << 3;
            const int gr = row0 + r;
            const __nv_bfloat16* gp =
                (gr < M) ? ((msel ? Al : Ah) + (size_t)gr * HH + c0) : Ah;
            const int sz = (gr < M) ? 16 : 0;
            const uint32_t d = smb + SMB_A + msel * A_SPLIT_B + r * A_STRIDE_B + c0 * 2;
            asm volatile("cp.async.cg.shared.global [%0], [%1], 16, %2;"
                         :: "r"(d), "l"(gp), "r"(sz));
        }
        asm volatile("cp.async.commit_group;");
    }

    // Build B fragment packs (once per CTA). Word j = ((ks*16+nb)*32+lane)*2+reg.
    // Fragment: b0 holds B[k0][n],B[k0+1][n] with k0 = ks*16+(lane&3)*2 (+8 for reg1),
    // n = nb*8 + (lane>>2).  B[k][n] = W[k*128+n].
    {
        uint32_t* Bh = (uint32_t*)(smc + SMB_BH);
        uint32_t* Bl = (uint32_t*)(smc + SMB_BL);
        for (int j = tid; j < 8192; j += 256) {
            const int reg = j & 1;
            const int ln = (j >> 1) & 31;
            const int nbks = j >> 6;              // 0..127
            const int nb = nbks & 15, ks = nbks >> 4;
            const int k = ks * 16 + (ln & 3) * 2 + reg * 8;
            const int n = nb * 8 + (ln >> 2);
            const float w0 = W[k * 128 + n];
            const float w1 = W[(k + 1) * 128 + n];
            const __nv_bfloat16 h0 = __float2bfloat16(w0);
            const __nv_bfloat16 h1 = __float2bfloat16(w1);
            const float l0f = w0 - __bfloat162float(h0);
            const float l1f = w1 - __bfloat162float(h1);
            __nv_bfloat162 hp; hp.x = h0; hp.y = h1;
            Bh[j] = *(uint32_t*)&hp;
            Bl[j] = bf2pack(l0f, l1f);
        }
    }

    asm volatile("cp.async.wait_group 0;");
    __syncthreads();

    // ldmatrix lane address (within current A buffer):
    // lanes 0-15 -> rows m0-15, k-low 8; lanes 16-31 -> rows m0-15, k-high 8.
    const uint32_t a_lane_off =
        (uint32_t)(w * 16 + (lane & 15)) * A_STRIDE_B + (uint32_t)((lane >> 4) * 8) * 2;

    const uint2* BhV = (const uint2*)(smc + SMB_BH);
    const uint2* BlV = (const uint2*)(smc + SMB_BL);

    int buf = 0;
    for (; tile < numTiles; tile += gridDim.x) {
        const int next = tile + gridDim.x;
        if (next < numTiles) {
            const int row0n = next * 128;
            const uint32_t abase = smb + SMB_A + (buf ^ 1) * A_BUF_B;
#pragma unroll
            for (int i = tid; i < 4096; i += 256) {
                const int msel = i >> 11;
                const int j = i & 2047;
                const int r = j >> 4, c0 = (j & 15) << 3;
                const int gr = row0n + r;
                const __nv_bfloat16* gp =
                    (gr < M) ? ((msel ? Al : Ah) + (size_t)gr * HH + c0) : Ah;
                const int sz = (gr < M) ? 16 : 0;
                const uint32_t d = abase + msel * A_SPLIT_B + r * A_STRIDE_B + c0 * 2;
                asm volatile("cp.async.cg.shared.global [%0], [%1], 16, %2;"
                             :: "r"(d), "l"(gp), "r"(sz));
            }
            asm volatile("cp.async.commit_group;");
        }

        // ---- Compute current tile ----
        const uint32_t abuf = smb + SMB_A + buf * A_BUF_B + a_lane_off;
        float acc[16][4];
#pragma unroll
        for (int nb = 0; nb < 16; nb++)
#pragma unroll
            for (int q = 0; q < 4; q++) acc[nb][q] = 0.0f;

#pragma unroll
        for (int ks = 0; ks < 8; ks++) {
            uint32_t ah[4], al[4];
            ldm_x4(ah, abuf + ks * 32);
            ldm_x4(al, abuf + A_SPLIT_B + ks * 32);
            const int bbase = ks * 16 * 32 + lane;
#pragma unroll
            for (int nb = 0; nb < 16; nb++) {
                const uint2 bh = BhV[bbase + nb * 32];
                const uint2 bl = BlV[bbase + nb * 32];
                mma16816(acc[nb], ah, bh.x, bh.y);
                mma16816(acc[nb], ah, bl.x, bl.y);
                mma16816(acc[nb], al, bh.x, bh.y);
            }
        }

        // ---- Epilogue: scale by dinv, store T' ----
        const int r0 = tile * 128 + w * 16 + (lane >> 2);
        const int r1 = r0 + 8;
        const float d0 = (r0 < M) ? g_deg[r0] : 0.0f;
        const float d1 = (r1 < M) ? g_deg[r1] : 0.0f;
#pragma unroll
        for (int nb = 0; nb < 16; nb++) {
            const int n = nb * 8 + (lane & 3) * 2;
            if (r0 < M) {
                float2 o; o.x = d0 * acc[nb][0]; o.y = d0 * acc[nb][1];
                *(float2*)&T[(size_t)r0 * HH + n] = o;
            }
            if (r1 < M) {
                float2 o; o.x = d1 * acc[nb][2]; o.y = d1 * acc[nb][3];
                *(float2*)&T[(size_t)r1 * HH + n] = o;
            }
        }

        asm volatile("cp.async.wait_group 0;");
        __syncthreads();
        buf ^= 1;
    }
}

// ---------------------------------------------------------------------------
// Aggregator: OUT[n] = dinv_n * (sum_{s->n} T'[s] + T'[n]) + bias, optional relu,
// written either as bf16 split (next GEMM input) or fp32 (pool input).
template <bool RELU, bool SPLIT>
__global__ void agg_kernel(const float* __restrict__ Tp, const float* __restrict__ bias,
                           float* __restrict__ OUTF) {
    const int n = (blockIdx.x * blockDim.x + threadIdx.x) >> 5;
    const int lane = threadIdx.x & 31;
    if (n >= NN) return;
    const int c = lane << 2;

    float4 acc = *(const float4*)(Tp + (size_t)n * HH + c);   // self term
    int i = g_rs[n];
    const int end = g_rs[n + 1];
    for (; i + 1 < end; i += 2) {
        const int s0 = g_csr[i];
        const int s1 = g_csr[i + 1];
        const float4 v0 = *(const float4*)(Tp + (size_t)s0 * HH + c);
        const float4 v1 = *(const float4*)(Tp + (size_t)s1 * HH + c);
        acc.x += v0.x; acc.y += v0.y; acc.z += v0.z; acc.w += v0.w;
        acc.x += v1.x; acc.y += v1.y; acc.z += v1.z; acc.w += v1.w;
    }
    if (i < end) {
        const int s0 = g_csr[i];
        const float4 v0 = *(const float4*)(Tp + (size_t)s0 * HH + c);
        acc.x += v0.x; acc.y += v0.y; acc.z += v0.z; acc.w += v0.w;
    }

    const float d = g_deg[n];
    const float4 b = *(const float4*)(bias + c);
    float4 o;
    o.x = fmaf(d, acc.x, b.x);
    o.y = fmaf(d, acc.y, b.y);
    o.z = fmaf(d, acc.z, b.z);
    o.w = fmaf(d, acc.w, b.w);
    if (RELU) {
        o.x = fmaxf(o.x, 0.f); o.y = fmaxf(o.y, 0.f);
        o.z = fmaxf(o.z, 0.f); o.w = fmaxf(o.w, 0.f);
    }
    if (SPLIT) {
        __nv_bfloat162 h01, h23, l01, l23;
        h01.x = __float2bfloat16(o.x); h01.y = __float2bfloat16(o.y);
        h23.x = __float2bfloat16(o.z); h23.y = __float2bfloat16(o.w);
        l01.x = __float2bfloat16(o.x - __bfloat162float(h01.x));
        l01.y = __float2bfloat16(o.y - __bfloat162float(h01.y));
        l23.x = __float2bfloat16(o.z - __bfloat162float(h23.x));
        l23.y = __float2bfloat16(o.w - __bfloat162float(h23.y));
        *(__nv_bfloat162*)&g_ah[(size_t)n * HH + c] = h01;
        *(__nv_bfloat162*)&g_ah[(size_t)n * HH + c + 2] = h23;
        *(__nv_bfloat162*)&g_al[(size_t)n * HH + c] = l01;
        *(__nv_bfloat162*)&g_al[(size_t)n * HH + c + 2] = l23;
    } else {
        *(float4*)(OUTF + (size_t)n * HH + c) = o;
    }
}

// ---------------------------------------------------------------------------
__global__ void pool_zero_kernel() {
    int i = blockIdx.x * blockDim.x + threadIdx.x;
    if (i < GG * HH) g_pool[i] = 0.0f;
    if (i < GG) g_cnt[i] = 0.0f;
}

__global__ void pool_scatter_kernel(const int* __restrict__ batch, const float* __restrict__ h) {
    const int n = (blockIdx.x * blockDim.x + threadIdx.x) >> 5;
    const int lane = threadIdx.x & 31;
    if (n >= NN) return;
    const int g = batch[n];
    float4 v = *(const float4*)(h + (size_t)n * HH + (lane << 2));
    float* p = g_pool + (size_t)g * HH + (lane << 2);
    asm volatile("red.global.add.v4.f32 [%0], {%1,%2,%3,%4};"
                 :: "l"(p), "f"(v.x), "f"(v.y), "f"(v.z), "f"(v.w)
                 : "memory");
    if (lane == 0) atomicAdd(&g_cnt[g], 1.0f);
}

// ---------------------------------------------------------------------------
// Final GEMM (SIMT f32x2, R12 proven): OUT = (pool/max(cnt,1)) @ Wl + bl
__global__ void __launch_bounds__(256, 1)
gemm_final_kernel(const float* __restrict__ A, const float* __restrict__ B,
                  const float* __restrict__ bias, float* __restrict__ OUT,
                  int M, int numTiles) {
    extern __shared__ float sm[];
    const int tid = threadIdx.x;
    const int tx = tid & 15;
    const int ty = tid >> 4;
    const int r0t = ty << 3;

    int tile = blockIdx.x;
    {
        const int row0 = tile * 128;
        float* dst = sm + 16384;
#pragma unroll
        for (int i = tid; i < 4096; i += 256) {
            const int r = i >> 5, c = (i & 31) << 2;
            const int gr = row0 + r;
            const float* gp = (gr < M) ? (A + (size_t)gr * HH + c) : A;
            const int sz = (gr < M) ? 16 : 0;
            const unsigned int d = (unsigned int)__cvta_generic_to_shared(&dst[r * 128 + c]);
            asm volatile("cp.async.cg.shared.global [%0], [%1], 16, %2;"
                         :: "r"(d), "l"(gp), "r"(sz));
        }
        asm volatile("cp.async.commit_group;");
    }
    {
        float2* Bp = (float2*)sm;
#pragma unroll
        for (int i = tid; i < 8192; i += 256) {
            const int kk = i >> 7, c = i & 127;
            Bp[i] = make_float2(B[(2 * kk) * 128 + c], B[(2 * kk + 1) * 128 + c]);
        }
    }
    float bsv[8];
#pragma unroll
    for (int q = 0; q < 4; q++) {
        const float2 b2 = *(const float2*)&bias[32 * q + 2 * tx];
        bsv[2 * q] = b2.x; bsv[2 * q + 1] = b2.y;
    }
    asm volatile("cp.async.wait_group 0;");
    __syncthreads();

    int buf = 0;
    const unsigned long long* BpU = (const unsigned long long*)sm;

    for (; tile < numTiles; tile += gridDim.x) {
        const int next = tile + gridDim.x;
        if (next < numTiles) {
            const int row0n = next * 128;
            float* dst = sm + 16384 + ((buf ^ 1) << 14);
#pragma unroll
            for (int i = tid; i < 4096; i += 256) {
                const int r = i >> 5, c = (i & 31) << 2;
                const int gr = row0n + r;
                const float* gp = (gr < M) ? (A + (size_t)gr * HH + c) : A;
                const int sz = (gr < M) ? 16 : 0;
                const unsigned int d = (unsigned int)__cvta_generic_to_shared(&dst[r * 128 + c]);
                asm volatile("cp.async.cg.shared.global [%0], [%1], 16, %2;"
                             :: "r"(d), "l"(gp), "r"(sz));
            }
            asm volatile("cp.async.commit_group;");
        }

        const float* As = sm + 16384 + (buf << 14);
        unsigned long long acc[8][8];
#pragma unroll
        for (int i = 0; i < 8; i++)
#pragma unroll
            for (int j = 0; j < 8; j++) acc[i][j] = 0ull;

#pragma unroll 2
        for (int kk = 0; kk < 64; kk++) {
            unsigned long long y[8];
            {
                const unsigned long long* yb = BpU + kk * 128 + 2 * tx;
                const ulonglong2 t0 = *(const ulonglong2*)(yb);
                const ulonglong2 t1 = *(const ulonglong2*)(yb + 32);
                const ulonglong2 t2 = *(const ulonglong2*)(yb + 64);
                const ulonglong2 t3 = *(const ulonglong2*)(yb + 96);
                y[0] = t0.x; y[1] = t0.y; y[2] = t1.x; y[3] = t1.y;
                y[4] = t2.x; y[5] = t2.y; y[6] = t3.x; y[7] = t3.y;
            }
#pragma unroll
            for (int i = 0; i < 8; i++) {
                const unsigned long long x =
                    *(const unsigned long long*)(As + (r0t + i) * 128 + 2 * kk);
#pragma unroll
                for (int j = 0; j < 8; j++)
                    asm("fma.rn.f32x2 %0, %1, %2, %0;" : "+l"(acc[i][j]) : "l"(x), "l"(y[j]));
            }
        }

        const int row0 = tile * 128;
#pragma unroll
        for (int i = 0; i < 8; i++) {
            const int r = row0 + r0t + i;
            if (r >= M) continue;
            float vv[8];
#pragma unroll
            for (int j = 0; j < 8; j++) {
                float lo, hi;
                asm("mov.b64 {%0, %1}, %2;" : "=f"(lo), "=f"(hi) : "l"(acc[i][j]));
                vv[j] = lo + hi;
            }
            const float s = 1.0f / fmaxf(g_cnt[r], 1.0f);
#pragma unroll
            for (int q = 0; q < 4; q++) {
                float2 o;
                o.x = fmaf(s, vv[2 * q], bsv[2 * q]);
                o.y = fmaf(s, vv[2 * q + 1], bsv[2 * q + 1]);
                *(float2*)&OUT[(size_t)r * TT + 32 * q + 2 * tx] = o;
            }
        }

        asm volatile("cp.async.wait_group 0;");
        __syncthreads();
        buf ^= 1;
    }
}

// ---------------------------------------------------------------------------
extern "C" void kernel_launch(void* const* d_in, const int* in_sizes, int n_in,
                              void* d_out, int out_size) {
    const int*   x     = (const int*)d_in[0];
    const int*   ei    = (const int*)d_in[1];
    const int*   batch = (const int*)d_in[2];
    const float* emb   = (const float*)d_in[3];
    const float* W1    = (const float*)d_in[4];
    const float* b1    = (const float*)d_in[5];
    const float* W2    = (const float*)d_in[6];
    const float* b2    = (const float*)d_in[7];
    const float* W3    = (const float*)d_in[8];
    const float* b3    = (const float*)d_in[9];
    const float* Wl    = (const float*)d_in[10];
    const float* bl    = (const float*)d_in[11];
    float* out = (float*)d_out;

    const int* srcp = ei;
    const int* dstp = ei + EE;

    float *p_t, *p_o, *p_pool;
    __nv_bfloat16 *p_ah, *p_al;
    cudaGetSymbolAddress((void**)&p_t, g_t);
    cudaGetSymbolAddress((void**)&p_o, g_o);
    cudaGetSymbolAddress((void**)&p_pool, g_pool);
    cudaGetSymbolAddress((void**)&p_ah, g_ah);
    cudaGetSymbolAddress((void**)&p_al, g_al);

    const int SMEM_F = 3 * 128 * 128 * (int)sizeof(float);   // 192KB
    static bool attr_set = false;
    if (!attr_set) {
        cudaFuncSetAttribute(gemm_mma_kernel, cudaFuncAttributeMaxDynamicSharedMemorySize, SMEM_MMA);
        cudaFuncSetAttribute(gemm_final_kernel, cudaFuncAttributeMaxDynamicSharedMemorySize, SMEM_F);
        attr_set = true;
    }

    // ---- CSR build (also computes dinv) ----
    count_zero_kernel<<<(NN + 255) / 256, 256>>>();
    count_kernel<<<(EE + 255) / 256, 256>>>(dstp);
    blocksum_kernel<<<NB, SCAN_B>>>();
    scanblock_kernel<<<1, 256>>>();
    rowstart_kernel<<<NB, SCAN_B>>>();
    fill_kernel<<<(EE + 255) / 256, 256>>>(srcp, dstp);

    // atom embedding sum -> split bf16
    embed_kernel<<<NN, 128>>>(x, emb);

    const int tilesN = (NN + 127) / 128;      // 782
    const int tilesG = (GG + 127) / 128;      // 32
    const int gridN = tilesN < 148 ? tilesN : 148;
    const int agg_blocks = (NN * 32 + 255) / 256;

    // Layer 1
    gemm_mma_kernel<<<gridN, 256, SMEM_MMA>>>(p_ah, p_al, W1, p_t, NN, tilesN);
    agg_kernel<true, true><<<agg_blocks, 256>>>(p_t, b1, nullptr);

    // Layer 2
    gemm_mma_kernel<<<gridN, 256, SMEM_MMA>>>(p_ah, p_al, W2, p_t, NN, tilesN);
    agg_kernel<true, true><<<agg_blocks, 256>>>(p_t, b2, nullptr);

    // Layer 3 (no relu, fp32 out for pool)
    gemm_mma_kernel<<<gridN, 256, SMEM_MMA>>>(p_ah, p_al, W3, p_t, NN, tilesN);
    agg_kernel<false, false><<<agg_blocks, 256>>>(p_t, b3, p_o);

    // Mean pool + final linear
    pool_zero_kernel<<<(GG * HH + 255) / 256, 256>>>();
    pool_scatter_kernel<<<(NN * 32 + 255) / 256, 256>>>(batch, p_o);
    gemm_final_kernel<<<(tilesG < 148 ? tilesG : 148), 256, SMEM_F>>>(p_pool, Wl, bl, out, GG, tilesG);
}

// round 17
// speedup vs baseline: 1.5294x; 1.0671x over previous
#include <cuda_runtime.h>
#include <cuda_bf16.h>
#include <cstdint>

// Problem constants (fixed shapes per reference)
#define NN 100000
#define EE 600000
#define HH 128
#define GG 4000
#define TT 128

#define SCAN_B 512
#define NB ((NN + SCAN_B - 1) / SCAN_B)

// Scratch (allocation-free: device globals)
__device__ float g_deg[NN];                       // dinv
__device__ float g_t[(size_t)NN * HH];            // T' = dinv * (A@B)
__device__ __nv_bfloat16 g_ah[(size_t)NN * HH];   // activation split hi
__device__ __nv_bfloat16 g_al[(size_t)NN * HH];   // activation split lo
__device__ float g_pool[(size_t)GG * HH];
__device__ float g_cnt[GG];
__device__ int   g_cnti[NN];
__device__ int   g_cur[NN];
__device__ int   g_rs[NN + 1];
__device__ int   g_csr[EE];
__device__ int   g_bsum[NB];

__constant__ int c_off[9] = {0, 119, 124, 136, 148, 158, 164, 170, 172};

// ---------------------------------------------------------------------------
// Combined zero-init: cnti/cur (NN), pool (GG*HH), cnt (GG)
__global__ void init_kernel() {
    int i = blockIdx.x * blockDim.x + threadIdx.x;
    if (i < NN) { g_cnti[i] = 0; g_cur[i] = 0; }
    if (i < GG * HH) g_pool[i] = 0.0f;
    if (i < GG) g_cnt[i] = 0.0f;
}
__global__ void count_kernel(const int* __restrict__ dst) {
    int e = blockIdx.x * blockDim.x + threadIdx.x;
    if (e < EE) atomicAdd(&g_cnti[dst[e]], 1);
}
__global__ void blocksum_kernel() {
    __shared__ int s[SCAN_B];
    const int n = blockIdx.x * SCAN_B + threadIdx.x;
    s[threadIdx.x] = (n < NN) ? g_cnti[n] : 0;
    __syncthreads();
    for (int off = SCAN_B / 2; off > 0; off >>= 1) {
        if (threadIdx.x < off) s[threadIdx.x] += s[threadIdx.x + off];
        __syncthreads();
    }
    if (threadIdx.x == 0) g_bsum[blockIdx.x] = s[0];
}
__global__ void scanblock_kernel() {
    __shared__ int s[256];
    const int t = threadIdx.x;
    const int v = (t < NB) ? g_bsum[t] : 0;
    s[t] = v;
    __syncthreads();
    for (int off = 1; off < 256; off <<= 1) {
        int u = (t >= off) ? s[t - off] : 0;
        __syncthreads();
        s[t] += u;
        __syncthreads();
    }
    if (t < NB) g_bsum[t] = s[t] - v;
}
__global__ void rowstart_kernel() {
    __shared__ int s[SCAN_B];
    const int t = threadIdx.x;
    const int n = blockIdx.x * SCAN_B + t;
    const int v = (n < NN) ? g_cnti[n] : 0;
    s[t] = v;
    __syncthreads();
    for (int off = 1; off < SCAN_B; off <<= 1) {
        int u = (t >= off) ? s[t - off] : 0;
        __syncthreads();
        s[t] += u;
        __syncthreads();
    }
    if (n < NN) {
        g_rs[n] = s[t] - v + g_bsum[blockIdx.x];
        g_deg[n] = rsqrtf((float)v + 1.0f);
    }
    if (blockIdx.x == 0 && t == 0) g_rs[NN] = EE;
}
__global__ void fill_kernel(const int* __restrict__ src, const int* __restrict__ dst) {
    int e = blockIdx.x * blockDim.x + threadIdx.x;
    if (e >= EE) return;
    const int d = dst[e];
    const int pos = g_rs[d] + atomicAdd(&g_cur[d], 1);
    g_csr[pos] = src[e];
}

// ---------------------------------------------------------------------------
// AtomEncoder: writes split bf16 activation
__global__ void embed_kernel(const int* __restrict__ x, const float* __restrict__ emb) {
    int n = blockIdx.x;
    int t = threadIdx.x;
    __shared__ int xi[9];
    if (t < 9) xi[t] = x[n * 9 + t] + c_off[t];
    __syncthreads();
    float v = 0.0f;
#pragma unroll
    for (int f = 0; f < 9; f++) v += emb[(size_t)xi[f] * HH + t];
    const __nv_bfloat16 hi = __float2bfloat16(v);
    const __nv_bfloat16 lo = __float2bfloat16(v - __bfloat162float(hi));
    g_ah[(size_t)n * HH + t] = hi;
    g_al[(size_t)n * HH + t] = lo;
}

// ---------------------------------------------------------------------------
// mma.sync helpers (base ISA — works on compute_103 target)
__device__ __forceinline__ void mma16816(float* c, const uint32_t* a,
                                         uint32_t b0, uint32_t b1) {
    asm volatile(
        "mma.sync.aligned.m16n8k16.row.col.f32.bf16.bf16.f32 "
        "{%0,%1,%2,%3}, {%4,%5,%6,%7}, {%8,%9}, {%0,%1,%2,%3};"
        : "+f"(c[0]), "+f"(c[1]), "+f"(c[2]), "+f"(c[3])
        : "r"(a[0]), "r"(a[1]), "r"(a[2]), "r"(a[3]), "r"(b0), "r"(b1));
}
__device__ __forceinline__ void ldm_x4(uint32_t* r, uint32_t addr) {
    asm volatile("ldmatrix.sync.aligned.m8n8.x4.shared.b16 {%0,%1,%2,%3}, [%4];"
                 : "=r"(r[0]), "=r"(r[1]), "=r"(r[2]), "=r"(r[3]) : "r"(addr));
}
__device__ __forceinline__ uint32_t smem_u32(const void* p) {
    uint32_t a;
    asm("{ .reg .u64 t; cvta.to.shared.u64 t, %1; cvt.u32.u64 %0, t; }" : "=r"(a) : "l"(p));
    return a;
}

// smem map (bytes): Bh pack [0,32768), Bl pack [32768,65536),
// A tiles: buf b, split s at 65536 + b*69632 + s*34816 (row stride 272B).
#define SMB_BH 0
#define SMB_BL 32768
#define SMB_A  65536
#define A_STRIDE_B 272
#define A_SPLIT_B 34816
#define A_BUF_B 69632
#define SMEM_MMA (65536 + 2 * A_BUF_B)   // 204800

// ---------------------------------------------------------------------------
// HMMA layer GEMM (persistent): T'[r] = dinv[r] * (A @ W)[r]
// A as bf16 split (Ah+Al); computes Ah*Wh + Ah*Wl + Al*Wh, fp32 accum in regs.
// 256 threads = 8 warps; warp w owns rows [w*16, w*16+16) x all 128 cols.
__global__ void __launch_bounds__(256, 1)
gemm_mma_kernel(const __nv_bfloat16* __restrict__ Ah, const __nv_bfloat16* __restrict__ Al,
                const float* __restrict__ W, float* __restrict__ T, int M, int numTiles) {
    extern __shared__ char smc[];
    const uint32_t smb = smem_u32(smc);
    const int tid = threadIdx.x;
    const int w = tid >> 5;
    const int lane = tid & 31;

    // Stage first A tile (buffer 0): 16B chunks into padded rows.
    int tile = blockIdx.x;
    {
        const int row0 = tile * 128;
#pragma unroll
        for (int i = tid; i < 4096; i += 256) {
            const int msel = i >> 11;            // 0 = hi, 1 = lo
            const int j = i & 2047;
            const int r = j >> 4, c0 = (j & 15) << 3;
            const int gr = row0 + r;
            const __nv_bfloat16* gp =
                (gr < M) ? ((msel ? Al : Ah) + (size_t)gr * HH + c0) : Ah;
            const int sz = (gr < M) ? 16 : 0;
            const uint32_t d = smb + SMB_A + msel * A_SPLIT_B + r * A_STRIDE_B + c0 * 2;
            asm volatile("cp.async.cg.shared.global [%0], [%1], 16, %2;"
                         :: "r"(d), "l"(gp), "r"(sz));
        }
        asm volatile("cp.async.commit_group;");
    }

    // Build B fragment packs (once per CTA), COALESCED on W:
    // iterate (k_even, n): consecutive threads read consecutive n.
    // Dest word index (inverse of fragment map):
    //   ks=k>>4, nb=n>>3, ln=((n&7)<<2)|((k&7)>>1), reg=(k&15)>>3,
    //   j=((ks*16+nb)*32+ln)*2+reg;  word = {B[k][n], B[k+1][n]} as bf16x2.
    {
        uint32_t* Bh = (uint32_t*)(smc + SMB_BH);
        uint32_t* Bl = (uint32_t*)(smc + SMB_BL);
        for (int idx = tid; idx < 8192; idx += 256) {
            const int keven = idx >> 7;          // 0..63
            const int n = idx & 127;
            const int k = keven << 1;
            const float w0 = W[k * 128 + n];
            const float w1 = W[(k + 1) * 128 + n];
            const __nv_bfloat16 h0 = __float2bfloat16(w0);
            const __nv_bfloat16 h1 = __float2bfloat16(w1);
            __nv_bfloat162 hp; hp.x = h0; hp.y = h1;
            __nv_bfloat162 lp;
            lp.x = __float2bfloat16(w0 - __bfloat162float(h0));
            lp.y = __float2bfloat16(w1 - __bfloat162float(h1));
            const int ks = k >> 4, nb = n >> 3;
            const int ln = ((n & 7) << 2) | ((k & 7) >> 1);
            const int reg = (k & 15) >> 3;
            const int j = ((ks * 16 + nb) * 32 + ln) * 2 + reg;
            Bh[j] = *(uint32_t*)&hp;
            Bl[j] = *(uint32_t*)&lp;
        }
    }

    asm volatile("cp.async.wait_group 0;");
    __syncthreads();

    // ldmatrix lane address (within current A buffer):
    // lanes 0-15 -> rows m0-15, k-low 8; lanes 16-31 -> rows m0-15, k-high 8.
    const uint32_t a_lane_off =
        (uint32_t)(w * 16 + (lane & 15)) * A_STRIDE_B + (uint32_t)((lane >> 4) * 8) * 2;

    const uint2* BhV = (const uint2*)(smc + SMB_BH);
    const uint2* BlV = (const uint2*)(smc + SMB_BL);

    int buf = 0;
    for (; tile < numTiles; tile += gridDim.x) {
        const int next = tile + gridDim.x;
        if (next < numTiles) {
            const int row0n = next * 128;
            const uint32_t abase = smb + SMB_A + (buf ^ 1) * A_BUF_B;
#pragma unroll
            for (int i = tid; i < 4096; i += 256) {
                const int msel = i >> 11;
                const int j = i & 2047;
                const int r = j >> 4, c0 = (j & 15) << 3;
                const int gr = row0n + r;
                const __nv_bfloat16* gp =
                    (gr < M) ? ((msel ? Al : Ah) + (size_t)gr * HH + c0) : Ah;
                const int sz = (gr < M) ? 16 : 0;
                const uint32_t d = abase + msel * A_SPLIT_B + r * A_STRIDE_B + c0 * 2;
                asm volatile("cp.async.cg.shared.global [%0], [%1], 16, %2;"
                             :: "r"(d), "l"(gp), "r"(sz));
            }
            asm volatile("cp.async.commit_group;");
        }

        // ---- Compute current tile ----
        const uint32_t abuf = smb + SMB_A + buf * A_BUF_B + a_lane_off;
        float acc[16][4];
#pragma unroll
        for (int nb = 0; nb < 16; nb++)
#pragma unroll
            for (int q = 0; q < 4; q++) acc[nb][q] = 0.0f;

#pragma unroll
        for (int ks = 0; ks < 8; ks++) {
            uint32_t ah[4], al[4];
            ldm_x4(ah, abuf + ks * 32);
            ldm_x4(al, abuf + A_SPLIT_B + ks * 32);
            const int bbase = ks * 16 * 32 + lane;
#pragma unroll
            for (int nb = 0; nb < 16; nb++) {
                const uint2 bh = BhV[bbase + nb * 32];
                const uint2 bl = BlV[bbase + nb * 32];
                mma16816(acc[nb], ah, bh.x, bh.y);
                mma16816(acc[nb], ah, bl.x, bl.y);
                mma16816(acc[nb], al, bh.x, bh.y);
            }
        }

        // ---- Epilogue: scale by dinv, store T' ----
        const int r0 = tile * 128 + w * 16 + (lane >> 2);
        const int r1 = r0 + 8;
        const float d0 = (r0 < M) ? g_deg[r0] : 0.0f;
        const float d1 = (r1 < M) ? g_deg[r1] : 0.0f;
#pragma unroll
        for (int nb = 0; nb < 16; nb++) {
            const int n = nb * 8 + (lane & 3) * 2;
            if (r0 < M) {
                float2 o; o.x = d0 * acc[nb][0]; o.y = d0 * acc[nb][1];
                *(float2*)&T[(size_t)r0 * HH + n] = o;
            }
            if (r1 < M) {
                float2 o; o.x = d1 * acc[nb][2]; o.y = d1 * acc[nb][3];
                *(float2*)&T[(size_t)r1 * HH + n] = o;
            }
        }

        asm volatile("cp.async.wait_group 0;");
        __syncthreads();
        buf ^= 1;
    }
}

// ---------------------------------------------------------------------------
// Aggregator: o[n] = dinv_n * (sum_{s->n} T'[s] + T'[n]) + bias.
// MODE 0: relu(o) -> bf16 split (next GEMM input).
// MODE 1: o -> red.add into g_pool[batch[n]] (fused mean-pool numerator) + cnt.
template <int MODE>
__global__ void agg_kernel(const float* __restrict__ Tp, const float* __restrict__ bias,
                           const int* __restrict__ batch) {
    const int n = (blockIdx.x * blockDim.x + threadIdx.x) >> 5;
    const int lane = threadIdx.x & 31;
    if (n >= NN) return;
    const int c = lane << 2;

    float4 acc = *(const float4*)(Tp + (size_t)n * HH + c);   // self term
    int i = g_rs[n];
    const int end = g_rs[n + 1];
    for (; i + 1 < end; i += 2) {
        const int s0 = g_csr[i];
        const int s1 = g_csr[i + 1];
        const float4 v0 = *(const float4*)(Tp + (size_t)s0 * HH + c);
        const float4 v1 = *(const float4*)(Tp + (size_t)s1 * HH + c);
        acc.x += v0.x; acc.y += v0.y; acc.z += v0.z; acc.w += v0.w;
        acc.x += v1.x; acc.y += v1.y; acc.z += v1.z; acc.w += v1.w;
    }
    if (i < end) {
        const int s0 = g_csr[i];
        const float4 v0 = *(const float4*)(Tp + (size_t)s0 * HH + c);
        acc.x += v0.x; acc.y += v0.y; acc.z += v0.z; acc.w += v0.w;
    }

    const float d = g_deg[n];
    const float4 b = *(const float4*)(bias + c);
    float4 o;
    o.x = fmaf(d, acc.x, b.x);
    o.y = fmaf(d, acc.y, b.y);
    o.z = fmaf(d, acc.z, b.z);
    o.w = fmaf(d, acc.w, b.w);

    if (MODE == 0) {
        o.x = fmaxf(o.x, 0.f); o.y = fmaxf(o.y, 0.f);
        o.z = fmaxf(o.z, 0.f); o.w = fmaxf(o.w, 0.f);
        __nv_bfloat162 h01, h23, l01, l23;
        h01.x = __float2bfloat16(o.x); h01.y = __float2bfloat16(o.y);
        h23.x = __float2bfloat16(o.z); h23.y = __float2bfloat16(o.w);
        l01.x = __float2bfloat16(o.x - __bfloat162float(h01.x));
        l01.y = __float2bfloat16(o.y - __bfloat162float(h01.y));
        l23.x = __float2bfloat16(o.z - __bfloat162float(h23.x));
        l23.y = __float2bfloat16(o.w - __bfloat162float(h23.y));
        *(__nv_bfloat162*)&g_ah[(size_t)n * HH + c] = h01;
        *(__nv_bfloat162*)&g_ah[(size_t)n * HH + c + 2] = h23;
        *(__nv_bfloat162*)&g_al[(size_t)n * HH + c] = l01;
        *(__nv_bfloat162*)&g_al[(size_t)n * HH + c + 2] = l23;
    } else {
        const int g = batch[n];
        float* p = g_pool + (size_t)g * HH + c;
        asm volatile("red.global.add.v4.f32 [%0], {%1,%2,%3,%4};"
                     :: "l"(p), "f"(o.x), "f"(o.y), "f"(o.z), "f"(o.w)
                     : "memory");
        if (lane == 0) atomicAdd(&g_cnt[g], 1.0f);
    }
}

// ---------------------------------------------------------------------------
// Final GEMM (SIMT f32x2): OUT = (pool/max(cnt,1)) @ Wl + bl
__global__ void __launch_bounds__(256, 1)
gemm_final_kernel(const float* __restrict__ A, const float* __restrict__ B,
                  const float* __restrict__ bias, float* __restrict__ OUT,
                  int M, int numTiles) {
    extern __shared__ float sm[];
    const int tid = threadIdx.x;
    const int tx = tid & 15;
    const int ty = tid >> 4;
    const int r0t = ty << 3;

    int tile = blockIdx.x;
    {
        const int row0 = tile * 128;
        float* dst = sm + 16384;
#pragma unroll
        for (int i = tid; i < 4096; i += 256) {
            const int r = i >> 5, c = (i & 31) << 2;
            const int gr = row0 + r;
            const float* gp = (gr < M) ? (A + (size_t)gr * HH + c) : A;
            const int sz = (gr < M) ? 16 : 0;
            const unsigned int d = (unsigned int)__cvta_generic_to_shared(&dst[r * 128 + c]);
            asm volatile("cp.async.cg.shared.global [%0], [%1], 16, %2;"
                         :: "r"(d), "l"(gp), "r"(sz));
        }
        asm volatile("cp.async.commit_group;");
    }
    {
        float2* Bp = (float2*)sm;
#pragma unroll
        for (int i = tid; i < 8192; i += 256) {
            const int kk = i >> 7, c = i & 127;
            Bp[i] = make_float2(B[(2 * kk) * 128 + c], B[(2 * kk + 1) * 128 + c]);
        }
    }
    float bsv[8];
#pragma unroll
    for (int q = 0; q < 4; q++) {
        const float2 b2 = *(const float2*)&bias[32 * q + 2 * tx];
        bsv[2 * q] = b2.x; bsv[2 * q + 1] = b2.y;
    }
    asm volatile("cp.async.wait_group 0;");
    __syncthreads();

    int buf = 0;
    const unsigned long long* BpU = (const unsigned long long*)sm;

    for (; tile < numTiles; tile += gridDim.x) {
        const int next = tile + gridDim.x;
        if (next < numTiles) {
            const int row0n = next * 128;
            float* dst = sm + 16384 + ((buf ^ 1) << 14);
#pragma unroll
            for (int i = tid; i < 4096; i += 256) {
                const int r = i >> 5, c = (i & 31) << 2;
                const int gr = row0n + r;
                const float* gp = (gr < M) ? (A + (size_t)gr * HH + c) : A;
                const int sz = (gr < M) ? 16 : 0;
                const unsigned int d = (unsigned int)__cvta_generic_to_shared(&dst[r * 128 + c]);
                asm volatile("cp.async.cg.shared.global [%0], [%1], 16, %2;"
                             :: "r"(d), "l"(gp), "r"(sz));
            }
            asm volatile("cp.async.commit_group;");
        }

        const float* As = sm + 16384 + (buf << 14);
        unsigned long long acc[8][8];
#pragma unroll
        for (int i = 0; i < 8; i++)
#pragma unroll
            for (int j = 0; j < 8; j++) acc[i][j] = 0ull;

#pragma unroll 2
        for (int kk = 0; kk < 64; kk++) {
            unsigned long long y[8];
            {
                const unsigned long long* yb = BpU + kk * 128 + 2 * tx;
                const ulonglong2 t0 = *(const ulonglong2*)(yb);
                const ulonglong2 t1 = *(const ulonglong2*)(yb + 32);
                const ulonglong2 t2 = *(const ulonglong2*)(yb + 64);
                const ulonglong2 t3 = *(const ulonglong2*)(yb + 96);
                y[0] = t0.x; y[1] = t0.y; y[2] = t1.x; y[3] = t1.y;
                y[4] = t2.x; y[5] = t2.y; y[6] = t3.x; y[7] = t3.y;
            }
#pragma unroll
            for (int i = 0; i < 8; i++) {
                const unsigned long long x =
                    *(const unsigned long long*)(As + (r0t + i) * 128 + 2 * kk);
#pragma unroll
                for (int j = 0; j < 8; j++)
                    asm("fma.rn.f32x2 %0, %1, %2, %0;" : "+l"(acc[i][j]) : "l"(x), "l"(y[j]));
            }
        }

        const int row0 = tile * 128;
#pragma unroll
        for (int i = 0; i < 8; i++) {
            const int r = row0 + r0t + i;
            if (r >= M) continue;
            float vv[8];
#pragma unroll
            for (int j = 0; j < 8; j++) {
                float lo, hi;
                asm("mov.b64 {%0, %1}, %2;" : "=f"(lo), "=f"(hi) : "l"(acc[i][j]));
                vv[j] = lo + hi;
            }
            const float s = 1.0f / fmaxf(g_cnt[r], 1.0f);
#pragma unroll
            for (int q = 0; q < 4; q++) {
                float2 o;
                o.x = fmaf(s, vv[2 * q], bsv[2 * q]);
                o.y = fmaf(s, vv[2 * q + 1], bsv[2 * q + 1]);
                *(float2*)&OUT[(size_t)r * TT + 32 * q + 2 * tx] = o;
            }
        }

        asm volatile("cp.async.wait_group 0;");
        __syncthreads();
        buf ^= 1;
    }
}

// ---------------------------------------------------------------------------
extern "C" void kernel_launch(void* const* d_in, const int* in_sizes, int n_in,
                              void* d_out, int out_size) {
    const int*   x     = (const int*)d_in[0];
    const int*   ei    = (const int*)d_in[1];
    const int*   batch = (const int*)d_in[2];
    const float* emb   = (const float*)d_in[3];
    const float* W1    = (const float*)d_in[4];
    const float* b1    = (const float*)d_in[5];
    const float* W2    = (const float*)d_in[6];
    const float* b2    = (const float*)d_in[7];
    const float* W3    = (const float*)d_in[8];
    const float* b3    = (const float*)d_in[9];
    const float* Wl    = (const float*)d_in[10];
    const float* bl    = (const float*)d_in[11];
    float* out = (float*)d_out;

    const int* srcp = ei;
    const int* dstp = ei + EE;

    float *p_t, *p_pool;
    __nv_bfloat16 *p_ah, *p_al;
    cudaGetSymbolAddress((void**)&p_t, g_t);
    cudaGetSymbolAddress((void**)&p_pool, g_pool);
    cudaGetSymbolAddress((void**)&p_ah, g_ah);
    cudaGetSymbolAddress((void**)&p_al, g_al);

    const int SMEM_F = 3 * 128 * 128 * (int)sizeof(float);   // 192KB
    static bool attr_set = false;
    if (!attr_set) {
        cudaFuncSetAttribute(gemm_mma_kernel, cudaFuncAttributeMaxDynamicSharedMemorySize, SMEM_MMA);
        cudaFuncSetAttribute(gemm_final_kernel, cudaFuncAttributeMaxDynamicSharedMemorySize, SMEM_F);
        attr_set = true;
    }

    // ---- init + CSR build (also computes dinv) ----
    init_kernel<<<(GG * HH + 255) / 256, 256>>>();
    count_kernel<<<(EE + 255) / 256, 256>>>(dstp);
    blocksum_kernel<<<NB, SCAN_B>>>();
    scanblock_kernel<<<1, 256>>>();
    rowstart_kernel<<<NB, SCAN_B>>>();
    fill_kernel<<<(EE + 255) / 256, 256>>>(srcp, dstp);

    // atom embedding sum -> split bf16
    embed_kernel<<<NN, 128>>>(x, emb);

    const int tilesN = (NN + 127) / 128;      // 782
    const int tilesG = (GG + 127) / 128;      // 32
    const int gridN = tilesN < 148 ? tilesN : 148;
    const int agg_blocks = (NN * 32 + 255) / 256;

    // Layer 1
    gemm_mma_kernel<<<gridN, 256, SMEM_MMA>>>(p_ah, p_al, W1, p_t, NN, tilesN);
    agg_kernel<0><<<agg_blocks, 256>>>(p_t, b1, nullptr);

    // Layer 2
    gemm_mma_kernel<<<gridN, 256, SMEM_MMA>>>(p_ah, p_al, W2, p_t, NN, tilesN);
    agg_kernel<0><<<agg_blocks, 256>>>(p_t, b2, nullptr);

    // Layer 3: agg fused with mean-pool scatter
    gemm_mma_kernel<<<gridN, 256, SMEM_MMA>>>(p_ah, p_al, W3, p_t, NN, tilesN);
    agg_kernel<1><<<agg_blocks, 256>>>(p_t, b3, batch);

    // Final linear on pooled means
    gemm_final_kernel<<<(tilesG < 148 ? tilesG : 148), 256, SMEM_F>>>(p_pool, Wl, bl, out, GG, tilesG);
}